// round 6
// baseline (speedup 1.0000x reference)
#include <cuda_runtime.h>
#include <cuda_bf16.h>
#include <math_constants.h>
#include <cstdint>

#define KC     200
#define NT     26            // total n-tiles of 8 -> KPAD = 208
#define NTW    13            // n-tiles per warp (pair-split)
#define KPAD   (NT * 8)
#define TILE_M 64
#define SMAX   60000
#define APITCH 72            // bf16 elems per smem row (144B, conflict-free)
#define NTS    25            // uint4 per Qc row (200 bf16)

// ---------------- scratch ----------------------------------------------------
__device__ __align__(16) __nv_bfloat16 g_Qc[(size_t)SMAX * KC + 8];

// ---------------- helpers ----------------------------------------------------
__device__ __forceinline__ uint32_t pack_bf2(float a, float b) {
    __nv_bfloat162 t = __floats2bfloat162_rn(a, b);   // a = low half
    return *(uint32_t*)&t;
}
__device__ __forceinline__ float blo(uint32_t u) {    // low bf16 -> f32 (exact)
    return __uint_as_float(u << 16);
}
__device__ __forceinline__ float bhi(uint32_t u) {    // high bf16 -> f32 (exact)
    return __uint_as_float(u & 0xffff0000u);
}

__device__ __forceinline__ void mma_bf16(float c[4], const uint32_t a[4],
                                         uint32_t b0, uint32_t b1) {
    asm volatile(
        "mma.sync.aligned.m16n8k16.row.col.f32.bf16.bf16.f32 "
        "{%0,%1,%2,%3}, {%4,%5,%6,%7}, {%8,%9}, {%0,%1,%2,%3};"
        : "+f"(c[0]), "+f"(c[1]), "+f"(c[2]), "+f"(c[3])
        : "r"(a[0]), "r"(a[1]), "r"(a[2]), "r"(a[3]), "r"(b0), "r"(b1));
}

// ---------------- K1: persistent fused logits+softmax+point+Qc ---------------
// smem layout (bytes)
#define OFF_CF  0                              // float4[KPAD]        3328
#define OFF_RC  (OFF_CF + KPAD * 16)           // float4[TILE_M]      1024
#define OFF_ST  (OFF_RC + TILE_M * 16)         // float[3][64][2]     1536
#define OFF_AH  (OFF_ST + 1536)
#define OFF_AL  (OFF_AH + TILE_M * APITCH * 2)
#define OFF_BH  (OFF_AL + TILE_M * APITCH * 2)
#define OFF_BL  (OFF_BH + KPAD * APITCH * 2)
#define SMEM_SZ (OFF_BL + KPAD * APITCH * 2)   // 84224 B

__global__ void __launch_bounds__(256, 2) k1_fused(
    const float* __restrict__ Z, const float* __restrict__ S,
    const float* __restrict__ sel_mu, const float* __restrict__ spa_mu,
    float* __restrict__ out, int s, float cpoint)
{
    extern __shared__ __align__(16) char smem[];
    float4* cfp = (float4*)(smem + OFF_CF);
    float4* rcp = (float4*)(smem + OFF_RC);
    float*  stM  = (float*)(smem + OFF_ST);          // [64][2]
    float*  stSE = stM + 128;
    float*  stSL = stSE + 128;
    __nv_bfloat16* Ah = (__nv_bfloat16*)(smem + OFF_AH);
    __nv_bfloat16* Al = (__nv_bfloat16*)(smem + OFF_AL);
    __nv_bfloat16* Bh = (__nv_bfloat16*)(smem + OFF_BH);
    __nv_bfloat16* Bl = (__nv_bfloat16*)(smem + OFF_BL);

    const int tid = threadIdx.x, lane = tid & 31, w = tid >> 5;
    const int g = lane >> 2, tg = lane & 3;
    const int stripe = w >> 1, half = w & 1;

    // ===== once per block: stage B (sel_mu) as bf16 hi/lo + cf =====
    #pragma unroll
    for (int it = 0; it < (KPAD * 16) / 256; ++it) {
        const int idx = it * 256 + tid;
        const int row = idx >> 4, j4 = idx & 15;
        float4 v = make_float4(0.f, 0.f, 0.f, 0.f);
        if (row < KC) v = ((const float4*)sel_mu)[row * 16 + j4];
        const float hx = __bfloat162float(__float2bfloat16(v.x));
        const float hy = __bfloat162float(__float2bfloat16(v.y));
        const float hz = __bfloat162float(__float2bfloat16(v.z));
        const float hw = __bfloat162float(__float2bfloat16(v.w));
        uint32_t* dh = (uint32_t*)(Bh + row * APITCH + j4 * 4);
        dh[0] = pack_bf2(hx, hy); dh[1] = pack_bf2(hz, hw);
        uint32_t* dl = (uint32_t*)(Bl + row * APITCH + j4 * 4);
        dl[0] = pack_bf2(v.x - hx, v.y - hy);
        dl[1] = pack_bf2(v.z - hz, v.w - hw);
    }
    if (tid < KPAD) {
        const int k = tid;
        float4 cf = make_float4(0.f, 0.f, 0.f, 1e30f);
        if (k < KC) {
            const float a = spa_mu[3 * k], b = spa_mu[3 * k + 1], c = spa_mu[3 * k + 2];
            float mn = a * a + b * b + c * c;
            const float4* mr = (const float4*)sel_mu + (size_t)k * 16;
            #pragma unroll
            for (int j = 0; j < 16; ++j) {
                float4 m = mr[j];
                mn += m.x * m.x + m.y * m.y + m.z * m.z + m.w * m.w;
            }
            cf = make_float4(a, b, c, 0.5f * mn);
        }
        cfp[k] = cf;
    }

    // ===== persistent tile loop =====
    for (int tile = blockIdx.x; tile * TILE_M < s; tile += gridDim.x) {
        const int i0 = tile * TILE_M;
        __syncthreads();   // previous iter fully consumed (and B ready, 1st iter)

        // ---- stage A (Z tile) as bf16 hi/lo ----
        #pragma unroll
        for (int it = 0; it < (TILE_M * 16) / 256; ++it) {
            const int idx = it * 256 + tid;
            const int row = idx >> 4, j4 = idx & 15;
            const int gi = i0 + row;
            float4 v = make_float4(0.f, 0.f, 0.f, 0.f);
            if (gi < s) v = ((const float4*)Z)[(size_t)gi * 16 + j4];
            const float hx = __bfloat162float(__float2bfloat16(v.x));
            const float hy = __bfloat162float(__float2bfloat16(v.y));
            const float hz = __bfloat162float(__float2bfloat16(v.z));
            const float hw = __bfloat162float(__float2bfloat16(v.w));
            uint32_t* dh = (uint32_t*)(Ah + row * APITCH + j4 * 4);
            dh[0] = pack_bf2(hx, hy); dh[1] = pack_bf2(hz, hw);
            uint32_t* dl = (uint32_t*)(Al + row * APITCH + j4 * 4);
            dl[0] = pack_bf2(v.x - hx, v.y - hy);
            dl[1] = pack_bf2(v.z - hz, v.w - hw);
        }

        // ---- per-row constants ----
        if (tid < TILE_M) {
            const int gi = i0 + tid;
            float4 rc = make_float4(0.f, 0.f, 0.f, 0.f);
            if (gi < s) {
                float zn = 0.f;
                const float4* zr = (const float4*)Z + (size_t)gi * 16;
                #pragma unroll
                for (int j = 0; j < 16; ++j) {
                    float4 z = zr[j];
                    zn += z.x * z.x + z.y * z.y + z.z * z.z + z.w * z.w;
                }
                rc.x = S[(size_t)3 * gi];
                rc.y = S[(size_t)3 * gi + 1];
                rc.z = S[(size_t)3 * gi + 2];
                rc.w = zn + rc.x * rc.x + rc.y * rc.y + rc.z * rc.z;
            }
            rcp[tid] = rc;
        }
        __syncthreads();

        // ---- MMA mainloop: acc[t] += Ah*Bh + Ah*Bl + Al*Bh ----
        float acc[NTW][4];
        #pragma unroll
        for (int t = 0; t < NTW; ++t)
            acc[t][0] = acc[t][1] = acc[t][2] = acc[t][3] = 0.f;

        const int r0 = stripe * 16 + g;
        #pragma unroll
        for (int ks = 0; ks < 4; ++ks) {
            const int kb = ks * 16 + 2 * tg;
            uint32_t a_h[4], a_l[4];
            a_h[0] = *(const uint32_t*)(Ah + r0 * APITCH + kb);
            a_h[1] = *(const uint32_t*)(Ah + (r0 + 8) * APITCH + kb);
            a_h[2] = *(const uint32_t*)(Ah + r0 * APITCH + kb + 8);
            a_h[3] = *(const uint32_t*)(Ah + (r0 + 8) * APITCH + kb + 8);
            a_l[0] = *(const uint32_t*)(Al + r0 * APITCH + kb);
            a_l[1] = *(const uint32_t*)(Al + (r0 + 8) * APITCH + kb);
            a_l[2] = *(const uint32_t*)(Al + r0 * APITCH + kb + 8);
            a_l[3] = *(const uint32_t*)(Al + (r0 + 8) * APITCH + kb + 8);
            #pragma unroll
            for (int t = 0; t < NTW; ++t) {
                const int tgl = half * NTW + t;
                const __nv_bfloat16* bh = Bh + (tgl * 8 + g) * APITCH + kb;
                const __nv_bfloat16* bl = Bl + (tgl * 8 + g) * APITCH + kb;
                const uint32_t bh0 = *(const uint32_t*)bh;
                const uint32_t bh1 = *(const uint32_t*)(bh + 8);
                const uint32_t bl0 = *(const uint32_t*)bl;
                const uint32_t bl1 = *(const uint32_t*)(bl + 8);
                mma_bf16(acc[t], a_h, bh0, bh1);
                mma_bf16(acc[t], a_h, bl0, bl1);
                mma_bf16(acc[t], a_l, bh0, bh1);
            }
        }

        // ---- epilogue: logits, warp-local softmax stats ----
        const float4 rc0 = rcp[r0];
        const float4 rc1 = rcp[r0 + 8];

        float m0 = -CUDART_INF_F, m1 = -CUDART_INF_F;
        #pragma unroll
        for (int t = 0; t < NTW; ++t) {
            const int cb = (half * NTW + t) * 8 + 2 * tg;
            const float4 c0 = cfp[cb];
            const float4 c1 = cfp[cb + 1];
            acc[t][0] += rc0.x * c0.x + rc0.y * c0.y + rc0.z * c0.z - c0.w;
            acc[t][1] += rc0.x * c1.x + rc0.y * c1.y + rc0.z * c1.z - c1.w;
            acc[t][2] += rc1.x * c0.x + rc1.y * c0.y + rc1.z * c0.z - c0.w;
            acc[t][3] += rc1.x * c1.x + rc1.y * c1.y + rc1.z * c1.z - c1.w;
            m0 = fmaxf(m0, fmaxf(acc[t][0], acc[t][1]));
            m1 = fmaxf(m1, fmaxf(acc[t][2], acc[t][3]));
        }
        m0 = fmaxf(m0, __shfl_xor_sync(0xffffffffu, m0, 1));
        m0 = fmaxf(m0, __shfl_xor_sync(0xffffffffu, m0, 2));
        m1 = fmaxf(m1, __shfl_xor_sync(0xffffffffu, m1, 1));
        m1 = fmaxf(m1, __shfl_xor_sync(0xffffffffu, m1, 2));

        float se0 = 0.f, sl0 = 0.f, se1 = 0.f, sl1 = 0.f;
        #pragma unroll
        for (int t = 0; t < NTW; ++t) {
            float e;
            e = __expf(acc[t][0] - m0); se0 += e; sl0 += e * acc[t][0]; acc[t][0] = e;
            e = __expf(acc[t][1] - m0); se0 += e; sl0 += e * acc[t][1]; acc[t][1] = e;
            e = __expf(acc[t][2] - m1); se1 += e; sl1 += e * acc[t][2]; acc[t][2] = e;
            e = __expf(acc[t][3] - m1); se1 += e; sl1 += e * acc[t][3]; acc[t][3] = e;
        }
        se0 += __shfl_xor_sync(0xffffffffu, se0, 1);
        se0 += __shfl_xor_sync(0xffffffffu, se0, 2);
        sl0 += __shfl_xor_sync(0xffffffffu, sl0, 1);
        sl0 += __shfl_xor_sync(0xffffffffu, sl0, 2);
        se1 += __shfl_xor_sync(0xffffffffu, se1, 1);
        se1 += __shfl_xor_sync(0xffffffffu, se1, 2);
        sl1 += __shfl_xor_sync(0xffffffffu, sl1, 1);
        sl1 += __shfl_xor_sync(0xffffffffu, sl1, 2);

        if (tg == 0) {
            stM [r0 * 2 + half] = m0;  stM [(r0 + 8) * 2 + half] = m1;
            stSE[r0 * 2 + half] = se0; stSE[(r0 + 8) * 2 + half] = se1;
            stSL[r0 * 2 + half] = sl0; stSL[(r0 + 8) * 2 + half] = sl1;
        }
        __syncthreads();

        float f0, f1;
        {
            const float ma = stM[r0 * 2], mb = stM[r0 * 2 + 1];
            const float M0 = fmaxf(ma, mb);
            const float wa = __expf(ma - M0), wb = __expf(mb - M0);
            const float seC = stSE[r0 * 2] * wa + stSE[r0 * 2 + 1] * wb;
            const float slC = stSL[r0 * 2] * wa + stSL[r0 * 2 + 1] * wb;
            const float inv0 = 1.0f / seC;
            f0 = __expf(m0 - M0) * inv0;
            const int gr = i0 + r0;
            if (half == 0 && tg == 0 && gr < s)
                out[gr] = 0.5f * rc0.w + cpoint - slC * inv0;
        }
        {
            const int r1 = r0 + 8;
            const float ma = stM[r1 * 2], mb = stM[r1 * 2 + 1];
            const float M1 = fmaxf(ma, mb);
            const float wa = __expf(ma - M1), wb = __expf(mb - M1);
            const float seC = stSE[r1 * 2] * wa + stSE[r1 * 2 + 1] * wb;
            const float slC = stSL[r1 * 2] * wa + stSL[r1 * 2 + 1] * wb;
            const float inv1 = 1.0f / seC;
            f1 = __expf(m1 - M1) * inv1;
            const int gr = i0 + r1;
            if (half == 0 && tg == 0 && gr < s)
                out[gr] = 0.5f * rc1.w + cpoint - slC * inv1;
        }

        // ---- store clipped Q as bf16 (point-major) ----
        const int gr0 = i0 + r0, gr1 = gr0 + 8;
        uint32_t* q0p = (uint32_t*)(g_Qc + (size_t)gr0 * KC);
        uint32_t* q1p = (uint32_t*)(g_Qc + (size_t)gr1 * KC);
        const bool v0 = (gr0 < s), v1 = (gr1 < s);
        const int tmax = NTW - half;   // half0: 13 tiles, half1: 12 (skip k>=200)
        #pragma unroll
        for (int t = 0; t < NTW; ++t) {
            if (t >= tmax) break;
            const int tgl = half * NTW + t;
            float qa = fminf(fmaxf(acc[t][0] * f0, 1e-6f), 1.0f - 1e-6f);
            float qb = fminf(fmaxf(acc[t][1] * f0, 1e-6f), 1.0f - 1e-6f);
            float qc = fminf(fmaxf(acc[t][2] * f1, 1e-6f), 1.0f - 1e-6f);
            float qd = fminf(fmaxf(acc[t][3] * f1, 1e-6f), 1.0f - 1e-6f);
            if (v0) q0p[4 * tgl + tg] = pack_bf2(qa, qb);
            if (v1) q1p[4 * tgl + tg] = pack_bf2(qc, qd);
        }
    }
}

// ---------------- K2: doublet energy (warp/point, bf16 rows) -----------------
template <bool IS64>
__device__ __forceinline__ void k2_body(float* __restrict__ out,
                                        const void* __restrict__ Dv,
                                        int s, int n, int i, int lane)
{
    const uint4* __restrict__ Q4 = (const uint4*)g_Qc;
    const uint4 zero4 = make_uint4(0, 0, 0, 0);
    const uint4 ov = (lane < NTS) ? Q4[(unsigned)i * NTS + lane] : zero4;
    float of[8];
    of[0] = blo(ov.x); of[1] = bhi(ov.x);
    of[2] = blo(ov.y); of[3] = bhi(ov.y);
    of[4] = blo(ov.z); of[5] = bhi(ov.z);
    of[6] = blo(ov.w); of[7] = bhi(ov.w);

    if (n == 6) {
        float acc[6]; bool val[6];
        #pragma unroll
        for (int nb = 0; nb < 6; ++nb) {
            long long d = IS64 ? ((const long long*)Dv)[(unsigned)i * 6 + nb]
                               : (long long)((const int*)Dv)[(unsigned)i * 6 + nb];
            const bool v = (d >= 0) && (d < (long long)s);
            val[nb] = v;
            const unsigned ridx = v ? (unsigned)d : (unsigned)i;
            const uint4 nv = (lane < NTS) ? Q4[ridx * NTS + lane] : zero4;
            float a = of[0] * blo(nv.x);
            a = fmaf(of[1], bhi(nv.x), a);
            a = fmaf(of[2], blo(nv.y), a);
            a = fmaf(of[3], bhi(nv.y), a);
            a = fmaf(of[4], blo(nv.z), a);
            a = fmaf(of[5], bhi(nv.z), a);
            a = fmaf(of[6], blo(nv.w), a);
            a = fmaf(of[7], bhi(nv.w), a);
            acc[nb] = a;
        }
        #pragma unroll
        for (int off = 16; off; off >>= 1) {
            #pragma unroll
            for (int nb = 0; nb < 6; ++nb)
                acc[nb] += __shfl_xor_sync(0xffffffffu, acc[nb], off);
        }
        if (lane == 0) {
            #pragma unroll
            for (int nb = 0; nb < 6; ++nb)
                if (!val[nb]) acc[nb] = 1.0f;
            const float p0 = acc[0] * acc[1];
            const float p1 = acc[2] * acc[3];
            const float p2 = acc[4] * acc[5];
            out[i] -= __logf(p0) + __logf(p1) + __logf(p2);
        }
    } else {
        float doublet = 0.f;
        for (int nb = 0; nb < n; ++nb) {
            long long d = IS64 ? ((const long long*)Dv)[(size_t)i * n + nb]
                               : (long long)((const int*)Dv)[(size_t)i * n + nb];
            const bool v = (d >= 0) && (d < (long long)s);
            const unsigned ridx = v ? (unsigned)d : (unsigned)i;
            const uint4 nv = (lane < NTS) ? Q4[ridx * NTS + lane] : zero4;
            float a = of[0] * blo(nv.x) + of[1] * bhi(nv.x)
                    + of[2] * blo(nv.y) + of[3] * bhi(nv.y)
                    + of[4] * blo(nv.z) + of[5] * bhi(nv.z)
                    + of[6] * blo(nv.w) + of[7] * bhi(nv.w);
            #pragma unroll
            for (int off = 16; off; off >>= 1)
                a += __shfl_xor_sync(0xffffffffu, a, off);
            if (v) doublet -= __logf(a);
        }
        if (lane == 0) out[i] += doublet;
    }
}

__global__ void __launch_bounds__(256, 3) k2_doublet(float* __restrict__ out,
                                                     const void* __restrict__ Dv,
                                                     int s, int n)
{
    const int t = threadIdx.x, lane = t & 31, w = t >> 5;

    // dtype probe: true int64 ids are all in [0, s); int32 data read as int64
    // packs two ids -> almost surely out of range somewhere in 32 words.
    const long long probe = ((const long long*)Dv)[lane];
    const bool ok = (probe >= 0) && (probe < (long long)s);
    const bool is64 = (__ballot_sync(0xffffffffu, ok) == 0xffffffffu);

    const int i = blockIdx.x * 8 + w;
    if (i >= s) return;

    if (is64) k2_body<true>(out, Dv, s, n, i, lane);
    else      k2_body<false>(out, Dv, s, n, i, lane);
}

// ---------------- launch -----------------------------------------------------
extern "C" void kernel_launch(void* const* d_in, const int* in_sizes, int n_in,
                              void* d_out, int out_size)
{
    const float* Z      = (const float*)d_in[0];
    const float* S      = (const float*)d_in[1];
    const void*  D      = d_in[2];
    const float* sel_mu = (const float*)d_in[3];
    const float* spa_mu = (const float*)d_in[4];
    float* out = (float*)d_out;

    const int s  = in_sizes[1] / 3;
    const int dz = in_sizes[0] / s;
    const int n  = in_sizes[2] / s;
    const float cpoint = 0.5f * (float)(dz + 3) * 1.8378770664093453f;

    static bool attr_set = false;
    if (!attr_set) {
        cudaFuncSetAttribute(k1_fused,
                             cudaFuncAttributeMaxDynamicSharedMemorySize,
                             SMEM_SZ);
        attr_set = true;
    }

    const int ntiles = (s + TILE_M - 1) / TILE_M;
    int grid = 296;                       // 2 blocks/SM persistent
    if (grid > ntiles) grid = ntiles;

    k1_fused<<<grid, 256, SMEM_SZ>>>(Z, S, sel_mu, spa_mu, out, s, cpoint);
    k2_doublet<<<(s + 7) / 8, 256>>>(out, D, s, n);
}

// round 7
// speedup vs baseline: 1.3303x; 1.3303x over previous
#include <cuda_runtime.h>
#include <cuda_fp16.h>
#include <cuda_bf16.h>
#include <math_constants.h>
#include <cstdint>

#define KC     200
#define NT     26            // total n-tiles of 8 -> KPAD = 208
#define NTW    13            // n-tiles per warp (pair-split)
#define KPAD   (NT * 8)
#define TILE_M 64
#define SMAX   60000
#define APITCH 72            // fp16 elems per smem row (144B, conflict-free)
#define NTS    25            // uint4 per Qc row (200 bf16)

// ---------------- scratch ----------------------------------------------------
__device__ __align__(16) __nv_bfloat16 g_Qc[(size_t)SMAX * KC + 8];

// ---------------- helpers ----------------------------------------------------
__device__ __forceinline__ uint32_t pack_h2(float a, float b) {
    __half2 t = __floats2half2_rn(a, b);   // a = low half
    return *(uint32_t*)&t;
}
__device__ __forceinline__ uint32_t pack_bf2(float a, float b) {
    __nv_bfloat162 t = __floats2bfloat162_rn(a, b);
    return *(uint32_t*)&t;
}

__device__ __forceinline__ void mma_f16(float c[4], const uint32_t a[4],
                                        uint32_t b0, uint32_t b1) {
    asm volatile(
        "mma.sync.aligned.m16n8k16.row.col.f32.f16.f16.f32 "
        "{%0,%1,%2,%3}, {%4,%5,%6,%7}, {%8,%9}, {%0,%1,%2,%3};"
        : "+f"(c[0]), "+f"(c[1]), "+f"(c[2]), "+f"(c[3])
        : "r"(a[0]), "r"(a[1]), "r"(a[2]), "r"(a[3]), "r"(b0), "r"(b1));
}

// ---------------- K1: fused fp16-HMMA logits + softmax + point + Qc ----------
__global__ void __launch_bounds__(256) k1_fused(
    const float* __restrict__ Z, const float* __restrict__ S,
    const float* __restrict__ sel_mu, const float* __restrict__ spa_mu,
    float* __restrict__ out, int s, float cpoint)
{
    __shared__ float4 cfp[KPAD];                 // (p0,p1,p2, 0.5*||mu||^2)
    __shared__ float4 rcp[TILE_M];               // (s0,s1,s2, ||x||^2)
    __shared__ float  stM[128], stSE[128], stSL[128];
    __shared__ __align__(16) __half Ah[TILE_M * APITCH];
    __shared__ __align__(16) __half Bh[KPAD * APITCH];

    const int tid = threadIdx.x, lane = tid & 31, w = tid >> 5;
    const int g = lane >> 2, tg = lane & 3;
    const int stripe = w >> 1, half = w & 1;
    const int i0 = blockIdx.x * TILE_M;

    // ---- stage B (sel_mu) as fp16 ----
    #pragma unroll
    for (int it = 0; it < (KPAD * 16) / 256; ++it) {
        const int idx = it * 256 + tid;
        const int row = idx >> 4, j4 = idx & 15;
        float4 v = make_float4(0.f, 0.f, 0.f, 0.f);
        if (row < KC) v = ((const float4*)sel_mu)[row * 16 + j4];
        uint32_t* dh = (uint32_t*)(Bh + row * APITCH + j4 * 4);
        dh[0] = pack_h2(v.x, v.y); dh[1] = pack_h2(v.z, v.w);
    }

    // ---- stage A (Z tile) as fp16 ----
    #pragma unroll
    for (int it = 0; it < (TILE_M * 16) / 256; ++it) {
        const int idx = it * 256 + tid;
        const int row = idx >> 4, j4 = idx & 15;
        const int gi = i0 + row;
        float4 v = make_float4(0.f, 0.f, 0.f, 0.f);
        if (gi < s) v = ((const float4*)Z)[(size_t)gi * 16 + j4];
        uint32_t* dh = (uint32_t*)(Ah + row * APITCH + j4 * 4);
        dh[0] = pack_h2(v.x, v.y); dh[1] = pack_h2(v.z, v.w);
    }

    // ---- per-cluster coefficients ----
    if (tid < KPAD) {
        const int k = tid;
        float4 cf = make_float4(0.f, 0.f, 0.f, 1e30f);
        if (k < KC) {
            const float a = spa_mu[3 * k], b = spa_mu[3 * k + 1], c = spa_mu[3 * k + 2];
            float mn = a * a + b * b + c * c;
            const float4* mr = (const float4*)sel_mu + (size_t)k * 16;
            #pragma unroll
            for (int j = 0; j < 16; ++j) {
                float4 m = mr[j];
                mn += m.x * m.x + m.y * m.y + m.z * m.z + m.w * m.w;
            }
            cf = make_float4(a, b, c, 0.5f * mn);
        }
        cfp[k] = cf;
    }

    // ---- per-row constants ----
    if (tid < TILE_M) {
        const int gi = i0 + tid;
        float4 rc = make_float4(0.f, 0.f, 0.f, 0.f);
        if (gi < s) {
            float zn = 0.f;
            const float4* zr = (const float4*)Z + (size_t)gi * 16;
            #pragma unroll
            for (int j = 0; j < 16; ++j) {
                float4 z = zr[j];
                zn += z.x * z.x + z.y * z.y + z.z * z.z + z.w * z.w;
            }
            rc.x = S[(size_t)3 * gi];
            rc.y = S[(size_t)3 * gi + 1];
            rc.z = S[(size_t)3 * gi + 2];
            rc.w = zn + rc.x * rc.x + rc.y * rc.y + rc.z * rc.z;
        }
        rcp[tid] = rc;
    }
    __syncthreads();

    // ---- MMA mainloop (single fp16 product) ----
    float acc[NTW][4];
    #pragma unroll
    for (int t = 0; t < NTW; ++t)
        acc[t][0] = acc[t][1] = acc[t][2] = acc[t][3] = 0.f;

    const int r0 = stripe * 16 + g;
    #pragma unroll
    for (int ks = 0; ks < 4; ++ks) {
        const int kb = ks * 16 + 2 * tg;
        uint32_t a[4];
        a[0] = *(const uint32_t*)(Ah + r0 * APITCH + kb);
        a[1] = *(const uint32_t*)(Ah + (r0 + 8) * APITCH + kb);
        a[2] = *(const uint32_t*)(Ah + r0 * APITCH + kb + 8);
        a[3] = *(const uint32_t*)(Ah + (r0 + 8) * APITCH + kb + 8);
        #pragma unroll
        for (int t = 0; t < NTW; ++t) {
            const int tgl = half * NTW + t;
            const __half* bp = Bh + (tgl * 8 + g) * APITCH + kb;
            const uint32_t b0 = *(const uint32_t*)bp;
            const uint32_t b1 = *(const uint32_t*)(bp + 8);
            mma_f16(acc[t], a, b0, b1);
        }
    }

    // ---- epilogue: logits, warp-local softmax stats ----
    const float4 rc0 = rcp[r0];
    const float4 rc1 = rcp[r0 + 8];

    float m0 = -CUDART_INF_F, m1 = -CUDART_INF_F;
    #pragma unroll
    for (int t = 0; t < NTW; ++t) {
        const int cb = (half * NTW + t) * 8 + 2 * tg;
        const float4 c0 = cfp[cb];
        const float4 c1 = cfp[cb + 1];
        acc[t][0] += rc0.x * c0.x + rc0.y * c0.y + rc0.z * c0.z - c0.w;
        acc[t][1] += rc0.x * c1.x + rc0.y * c1.y + rc0.z * c1.z - c1.w;
        acc[t][2] += rc1.x * c0.x + rc1.y * c0.y + rc1.z * c0.z - c0.w;
        acc[t][3] += rc1.x * c1.x + rc1.y * c1.y + rc1.z * c1.z - c1.w;
        m0 = fmaxf(m0, fmaxf(acc[t][0], acc[t][1]));
        m1 = fmaxf(m1, fmaxf(acc[t][2], acc[t][3]));
    }
    m0 = fmaxf(m0, __shfl_xor_sync(0xffffffffu, m0, 1));
    m0 = fmaxf(m0, __shfl_xor_sync(0xffffffffu, m0, 2));
    m1 = fmaxf(m1, __shfl_xor_sync(0xffffffffu, m1, 1));
    m1 = fmaxf(m1, __shfl_xor_sync(0xffffffffu, m1, 2));

    float se0 = 0.f, sl0 = 0.f, se1 = 0.f, sl1 = 0.f;
    #pragma unroll
    for (int t = 0; t < NTW; ++t) {
        float e;
        e = __expf(acc[t][0] - m0); se0 += e; sl0 += e * acc[t][0]; acc[t][0] = e;
        e = __expf(acc[t][1] - m0); se0 += e; sl0 += e * acc[t][1]; acc[t][1] = e;
        e = __expf(acc[t][2] - m1); se1 += e; sl1 += e * acc[t][2]; acc[t][2] = e;
        e = __expf(acc[t][3] - m1); se1 += e; sl1 += e * acc[t][3]; acc[t][3] = e;
    }
    se0 += __shfl_xor_sync(0xffffffffu, se0, 1);
    se0 += __shfl_xor_sync(0xffffffffu, se0, 2);
    sl0 += __shfl_xor_sync(0xffffffffu, sl0, 1);
    sl0 += __shfl_xor_sync(0xffffffffu, sl0, 2);
    se1 += __shfl_xor_sync(0xffffffffu, se1, 1);
    se1 += __shfl_xor_sync(0xffffffffu, se1, 2);
    sl1 += __shfl_xor_sync(0xffffffffu, sl1, 1);
    sl1 += __shfl_xor_sync(0xffffffffu, sl1, 2);

    if (tg == 0) {
        stM [r0 * 2 + half] = m0;  stM [(r0 + 8) * 2 + half] = m1;
        stSE[r0 * 2 + half] = se0; stSE[(r0 + 8) * 2 + half] = se1;
        stSL[r0 * 2 + half] = sl0; stSL[(r0 + 8) * 2 + half] = sl1;
    }
    __syncthreads();

    float f0, f1;
    {
        const float ma = stM[r0 * 2], mb = stM[r0 * 2 + 1];
        const float M0 = fmaxf(ma, mb);
        const float wa = __expf(ma - M0), wb = __expf(mb - M0);
        const float seC = stSE[r0 * 2] * wa + stSE[r0 * 2 + 1] * wb;
        const float slC = stSL[r0 * 2] * wa + stSL[r0 * 2 + 1] * wb;
        const float inv0 = 1.0f / seC;
        f0 = __expf(m0 - M0) * inv0;
        const int gr = i0 + r0;
        if (half == 0 && tg == 0 && gr < s)
            out[gr] = 0.5f * rc0.w + cpoint - slC * inv0;
    }
    {
        const int r1 = r0 + 8;
        const float ma = stM[r1 * 2], mb = stM[r1 * 2 + 1];
        const float M1 = fmaxf(ma, mb);
        const float wa = __expf(ma - M1), wb = __expf(mb - M1);
        const float seC = stSE[r1 * 2] * wa + stSE[r1 * 2 + 1] * wb;
        const float slC = stSL[r1 * 2] * wa + stSL[r1 * 2 + 1] * wb;
        const float inv1 = 1.0f / seC;
        f1 = __expf(m1 - M1) * inv1;
        const int gr = i0 + r1;
        if (half == 0 && tg == 0 && gr < s)
            out[gr] = 0.5f * rc1.w + cpoint - slC * inv1;
    }

    // ---- store clipped Q as bf16 (point-major) ----
    const int gr0 = i0 + r0, gr1 = gr0 + 8;
    uint32_t* q0p = (uint32_t*)(g_Qc + (size_t)gr0 * KC);
    uint32_t* q1p = (uint32_t*)(g_Qc + (size_t)gr1 * KC);
    const bool v0 = (gr0 < s), v1 = (gr1 < s);
    const int tmax = NTW - half;   // half0: 13 tiles, half1: 12 (skip k>=200)
    #pragma unroll
    for (int t = 0; t < NTW; ++t) {
        if (t >= tmax) break;
        const int tgl = half * NTW + t;
        float qa = fminf(fmaxf(acc[t][0] * f0, 1e-6f), 1.0f - 1e-6f);
        float qb = fminf(fmaxf(acc[t][1] * f0, 1e-6f), 1.0f - 1e-6f);
        float qc = fminf(fmaxf(acc[t][2] * f1, 1e-6f), 1.0f - 1e-6f);
        float qd = fminf(fmaxf(acc[t][3] * f1, 1e-6f), 1.0f - 1e-6f);
        if (v0) q0p[4 * tgl + tg] = pack_bf2(qa, qb);
        if (v1) q1p[4 * tgl + tg] = pack_bf2(qc, qd);
    }
}

// ---------------- K2: doublet energy (R5 structure + log pairing) ------------
__global__ void __launch_bounds__(256) k2_doublet(float* __restrict__ out,
                                                  const void* __restrict__ Dv,
                                                  int s, int n)
{
    const int t = threadIdx.x, lane = t & 31, w = t >> 5;

    // dtype probe: true int64 ids are all in [0, s); int32 data read as int64
    // packs two ids -> almost surely out of range somewhere in 32 words.
    const long long probe = ((const long long*)Dv)[lane];
    const bool ok = (probe >= 0) && (probe < (long long)s);
    const bool is64 = (__ballot_sync(0xffffffffu, ok) == 0xffffffffu);

    const int i = blockIdx.x * 8 + w;
    if (i >= s) return;

    const uint4* Q4 = (const uint4*)g_Qc;   // row = 25 uint4 (200 bf16)
    const uint4 zero4 = make_uint4(0, 0, 0, 0);
    const uint4 ov = (lane < NTS) ? Q4[(size_t)i * NTS + lane] : zero4;
    float of[8];
    {
        const uint32_t* p = (const uint32_t*)&ov;
        #pragma unroll
        for (int j = 0; j < 4; ++j) {
            float2 f = __bfloat1622float2(*(const __nv_bfloat162*)&p[j]);
            of[2 * j] = f.x; of[2 * j + 1] = f.y;
        }
    }

    float doublet = 0.f;
    for (int base = 0; base < n; base += 6) {
        float acc[6]; int val[6];
        #pragma unroll
        for (int nb = 0; nb < 6; ++nb) {
            acc[nb] = 1.f; val[nb] = 0;
            const int q = base + nb;
            if (q < n) {
                long long d = is64 ? ((const long long*)Dv)[(size_t)i * n + q]
                                   : (long long)((const int*)Dv)[(size_t)i * n + q];
                val[nb] = (d >= 0 && d < s) ? 1 : 0;
                const size_t ridx = (size_t)(val[nb] ? (int)d : i) * NTS;
                const uint4 nv = (lane < NTS) ? Q4[ridx + lane] : zero4;
                const uint32_t* p = (const uint32_t*)&nv;
                float a = 0.f;
                #pragma unroll
                for (int j = 0; j < 4; ++j) {
                    float2 f = __bfloat1622float2(*(const __nv_bfloat162*)&p[j]);
                    a += of[2 * j] * f.x + of[2 * j + 1] * f.y;
                }
                acc[nb] = a;
            }
        }
        #pragma unroll
        for (int off = 16; off; off >>= 1) {
            #pragma unroll
            for (int nb = 0; nb < 6; ++nb)
                acc[nb] += __shfl_xor_sync(0xffffffffu, acc[nb], off);
        }
        #pragma unroll
        for (int nb = 0; nb < 6; ++nb)
            if (!val[nb]) acc[nb] = 1.0f;
        doublet -= __logf(acc[0] * acc[1]) + __logf(acc[2] * acc[3])
                 + __logf(acc[4] * acc[5]);
    }
    if (lane == 0) out[i] += doublet;
}

// ---------------- launch -----------------------------------------------------
extern "C" void kernel_launch(void* const* d_in, const int* in_sizes, int n_in,
                              void* d_out, int out_size)
{
    const float* Z      = (const float*)d_in[0];
    const float* S      = (const float*)d_in[1];
    const void*  D      = d_in[2];
    const float* sel_mu = (const float*)d_in[3];
    const float* spa_mu = (const float*)d_in[4];
    float* out = (float*)d_out;

    const int s  = in_sizes[1] / 3;
    const int dz = in_sizes[0] / s;
    const int n  = in_sizes[2] / s;
    const float cpoint = 0.5f * (float)(dz + 3) * 1.8378770664093453f;

    k1_fused<<<(s + TILE_M - 1) / TILE_M, 256>>>(
        Z, S, sel_mu, spa_mu, out, s, cpoint);
    k2_doublet<<<(s + 7) / 8, 256>>>(out, D, s, n);
}